// round 16
// baseline (speedup 1.0000x reference)
#include <cuda_runtime.h>
#include <cuda_fp16.h>
#include <math.h>
#include <stdint.h>

#define N_NODES 100000
#define N_EDGES 1600000
#define D 128
#define NEG_SLOPE 0.2f
#define INV_SQRT_D 0.08838834764831843f

#define SCAN_CHUNK 512
#define NBLK_SCAN ((N_NODES + SCAN_CHUNK - 1) / SCAN_CHUNK)   // 196

// ---------------- scratch (no allocs allowed) ----------------
__device__ __half g_hq[N_NODES * D];      // fp16: feeds qagg sum only
__device__ float  g_kact[N_NODES * D];    // fp32: score accuracy anchor
__device__ __half g_hproj[N_NODES * D];   // fp16: feeds alpha-weighted sum
__device__ __half g_qagg[N_NODES * D];    // fp16: gathered per edge in score pass
__device__ float  g_escore[N_EDGES];
__device__ int    g_cnt[N_NODES];         // zero at load; re-zeroed by score_weighted
__device__ int    g_off[N_NODES + 1];
__device__ int    g_cursor[N_NODES];
__device__ int    g_ecol[N_EDGES];
__device__ int    g_blocksum[NBLK_SCAN];
__device__ int    g_blockbase[NBLK_SCAN];
// W pre-split to bf16 hi/lo, [n][k-pair] layout packed bf16x2 (low16 = even k)
__device__ uint32_t g_Wbh[3 * D * (D / 2)];
__device__ uint32_t g_Wbl[3 * D * (D / 2)];

__device__ __forceinline__ float leaky(float v) {
    return v > 0.0f ? v : NEG_SLOPE * v;
}

__device__ __forceinline__ uint32_t pack_bf16(float lo_elem, float hi_elem) {
    uint32_t r;
    asm("cvt.rn.bf16x2.f32 %0, %1, %2;" : "=r"(r) : "f"(hi_elem), "f"(lo_elem));
    return r;
}
__device__ __forceinline__ float bf16hi_to_f(float v) {
    uint32_t r;
    asm("cvt.rn.bf16x2.f32 %0, %1, %2;" : "=r"(r) : "f"(0.f), "f"(v));
    return __uint_as_float(r << 16);
}
__device__ __forceinline__ void bf16split(float v, float& hi, float& lo) {
    hi = bf16hi_to_f(v);
    lo = v - hi;
}

// ================= W precompute (bf16 split, [n][kpair] layout) ============
__global__ void wsplit_kernel(const float* __restrict__ Wq,
                              const float* __restrict__ Wk,
                              const float* __restrict__ Wl) {
    int i = blockIdx.x * blockDim.x + threadIdx.x;
    if (i >= 3 * D * (D / 2)) return;
    int wi = i / (D * (D / 2));
    int rem = i % (D * (D / 2));
    int n = rem >> 6;
    int kp = rem & 63;
    const float* W = (wi == 0) ? Wq : ((wi == 1) ? Wk : Wl);
    float v0 = __ldg(W + (2 * kp) * D + n);
    float v1 = __ldg(W + (2 * kp + 1) * D + n);
    float h0, l0, h1, l1;
    bf16split(v0, h0, l0);
    bf16split(v1, h1, l1);
    g_Wbh[i] = pack_bf16(h0, h1);
    g_Wbl[i] = pack_bf16(l0, l1);
}

// ================= CSR scans =================
__global__ void scan1_kernel() {
    __shared__ int s[SCAN_CHUNK];
    int b = blockIdx.x, t = threadIdx.x;
    int i = b * SCAN_CHUNK + t;
    int v = (i < N_NODES) ? g_cnt[i] : 0;
    s[t] = v;
    __syncthreads();
    for (int off = 1; off < SCAN_CHUNK; off <<= 1) {
        int add = (t >= off) ? s[t - off] : 0;
        __syncthreads();
        s[t] += add;
        __syncthreads();
    }
    if (i < N_NODES) g_off[i] = s[t] - v;
    if (t == SCAN_CHUNK - 1) g_blocksum[b] = s[t];
}

__global__ void scan2_kernel() {
    __shared__ int s[256];
    int t = threadIdx.x;
    int v = (t < NBLK_SCAN) ? g_blocksum[t] : 0;
    s[t] = v;
    __syncthreads();
    for (int off = 1; off < 256; off <<= 1) {
        int add = (t >= off) ? s[t - off] : 0;
        __syncthreads();
        s[t] += add;
        __syncthreads();
    }
    if (t < NBLK_SCAN) g_blockbase[t] = s[t] - v;
}

__global__ void scan3_kernel() {
    int i = blockIdx.x * blockDim.x + threadIdx.x;
    if (i < N_NODES) {
        int o = g_off[i] + g_blockbase[i / SCAN_CHUNK];
        g_off[i] = o;
        g_cursor[i] = o;
    }
    if (i == 0) g_off[N_NODES] = N_EDGES;
}

__global__ void scatter_kernel(const int* __restrict__ row,
                               const int* __restrict__ col) {
    int e = blockIdx.x * blockDim.x + threadIdx.x;
    if (e >= N_EDGES) return;
    int r = __ldg(row + e);
    int pos = atomicAdd(&g_cursor[r], 1);
    g_ecol[pos] = __ldg(col + e);
}

// ====== fused: bf16 split-3 TC GEMM (blocks < 3*GB) + edge histogram ======
#define GBM 128
#define GBK 32
#define LDP 20   // u32 row stride for [*][16] pair arrays; conflict-free
#define GEMM_BLOCKS_X ((N_NODES + GBM - 1) / GBM)     // 782
#define GEMM_BLOCKS (3 * GEMM_BLOCKS_X)               // 2346
#define HIST_BLOCKS ((N_EDGES + 255) / 256)           // 6250

__device__ __forceinline__ void mma_bf16(float c[4], const uint32_t a[4],
                                         const uint32_t b0, const uint32_t b1) {
    asm volatile(
        "mma.sync.aligned.m16n8k16.row.col.f32.bf16.bf16.f32 "
        "{%0,%1,%2,%3}, {%4,%5,%6,%7}, {%8,%9}, {%0,%1,%2,%3};"
        : "+f"(c[0]), "+f"(c[1]), "+f"(c[2]), "+f"(c[3])
        : "r"(a[0]), "r"(a[1]), "r"(a[2]), "r"(a[3]), "r"(b0), "r"(b1));
}

__global__ __launch_bounds__(256, 2)
void gemm3_hist_kernel(const float* __restrict__ x,
                       const float* __restrict__ bl,
                       const int* __restrict__ row) {
    // ---------- hist branch: trailing blocks ----------
    if (blockIdx.x >= GEMM_BLOCKS) {
        int e = (blockIdx.x - GEMM_BLOCKS) * 256 + threadIdx.x;
        if (e < N_EDGES) atomicAdd(&g_cnt[__ldg(row + e)], 1);
        return;
    }

    // ---------- GEMM branch (round-6/9 proven inner loop) ----------
    __shared__ uint32_t Ahi[GBM * LDP];   // [row][kpair]
    __shared__ uint32_t Alo[GBM * LDP];
    __shared__ uint32_t Whi[D * LDP];     // [n][kpair] for this k0 tile
    __shared__ uint32_t Wlo[D * LDP];

    const int wi = blockIdx.x / GEMM_BLOCKS_X;
    const int bx = blockIdx.x % GEMM_BLOCKS_X;
    const uint32_t* __restrict__ gwh = g_Wbh + wi * D * (D / 2);
    const uint32_t* __restrict__ gwl = g_Wbl + wi * D * (D / 2);

    const int rowBase = bx * GBM;
    const int tid = threadIdx.x;
    const int lane = tid & 31;
    const int warp = tid >> 5;
    const int m_base = (warp & 3) * 32;
    const int n_base = (warp >> 2) * 64;
    const int lq = lane >> 2;
    const int lr = lane & 3;

    float c[2][8][4];
#pragma unroll
    for (int mt = 0; mt < 2; mt++)
#pragma unroll
        for (int nt = 0; nt < 8; nt++)
#pragma unroll
            for (int i = 0; i < 4; i++) c[mt][nt][i] = 0.f;

    for (int k0 = 0; k0 < D; k0 += GBK) {
        const int kp0 = k0 / 2;
#pragma unroll
        for (int i = tid; i < (GBM * GBK) / 4; i += 256) {
            int r = i >> 3;
            int c4 = (i & 7) << 2;
            int gr = rowBase + r;
            float4 v = make_float4(0.f, 0.f, 0.f, 0.f);
            if (gr < N_NODES)
                v = *(const float4*)(x + (size_t)gr * D + k0 + c4);
            float h0, l0, h1, l1, h2, l2, h3, l3;
            bf16split(v.x, h0, l0);
            bf16split(v.y, h1, l1);
            bf16split(v.z, h2, l2);
            bf16split(v.w, h3, l3);
            int idx = r * LDP + (c4 >> 1);
            Ahi[idx + 0] = pack_bf16(h0, h1);
            Ahi[idx + 1] = pack_bf16(h2, h3);
            Alo[idx + 0] = pack_bf16(l0, l1);
            Alo[idx + 1] = pack_bf16(l2, l3);
        }
#pragma unroll
        for (int i = tid; i < (D * GBK / 2) / 4; i += 256) {
            int n = i >> 2;
            int pg = (i & 3) << 2;
            uint4 vh = *(const uint4*)(gwh + (size_t)n * (D / 2) + kp0 + pg);
            uint4 vl = *(const uint4*)(gwl + (size_t)n * (D / 2) + kp0 + pg);
            *(uint4*)&Whi[n * LDP + pg] = vh;
            *(uint4*)&Wlo[n * LDP + pg] = vl;
        }
        __syncthreads();

#pragma unroll
        for (int ks = 0; ks < GBK / 16; ks++) {
            const int kb = ks * 8;
            uint32_t a_hi[2][4], a_lo[2][4];
#pragma unroll
            for (int mt = 0; mt < 2; mt++) {
                int r0 = m_base + mt * 16 + lq;
                a_hi[mt][0] = Ahi[r0 * LDP + kb + lr];
                a_hi[mt][1] = Ahi[(r0 + 8) * LDP + kb + lr];
                a_hi[mt][2] = Ahi[r0 * LDP + kb + lr + 4];
                a_hi[mt][3] = Ahi[(r0 + 8) * LDP + kb + lr + 4];
                a_lo[mt][0] = Alo[r0 * LDP + kb + lr];
                a_lo[mt][1] = Alo[(r0 + 8) * LDP + kb + lr];
                a_lo[mt][2] = Alo[r0 * LDP + kb + lr + 4];
                a_lo[mt][3] = Alo[(r0 + 8) * LDP + kb + lr + 4];
            }
#pragma unroll
            for (int nt = 0; nt < 8; nt++) {
                int n0 = n_base + nt * 8 + lq;
                uint32_t b0h = Whi[n0 * LDP + kb + lr];
                uint32_t b1h = Whi[n0 * LDP + kb + lr + 4];
                uint32_t b0l = Wlo[n0 * LDP + kb + lr];
                uint32_t b1l = Wlo[n0 * LDP + kb + lr + 4];
#pragma unroll
                for (int mt = 0; mt < 2; mt++) {
                    mma_bf16(c[mt][nt], a_hi[mt], b0h, b1h);
                    mma_bf16(c[mt][nt], a_hi[mt], b0l, b1l);
                    mma_bf16(c[mt][nt], a_lo[mt], b0h, b1h);
                }
            }
        }
        __syncthreads();
    }

#pragma unroll
    for (int mt = 0; mt < 2; mt++) {
#pragma unroll
        for (int half = 0; half < 2; half++) {
            int gr = rowBase + m_base + mt * 16 + lq + half * 8;
            if (gr >= N_NODES) continue;
#pragma unroll
            for (int nt = 0; nt < 8; nt++) {
                int gc = n_base + nt * 8 + lr * 2;
                float v0 = c[mt][nt][half * 2 + 0];
                float v1 = c[mt][nt][half * 2 + 1];
                if (wi == 0) {
                    *(__half2*)(g_hq + (size_t)gr * D + gc) =
                        __floats2half2_rn(v0, v1);
                } else if (wi == 1) {
                    v0 = leaky(v0);
                    v1 = leaky(v1);
                    *(float2*)(g_kact + (size_t)gr * D + gc) = make_float2(v0, v1);
                } else {
                    v0 += __ldg(bl + gc + 0);
                    v1 += __ldg(bl + gc + 1);
                    *(__half2*)(g_hproj + (size_t)gr * D + gc) =
                        __floats2half2_rn(v0, v1);
                }
            }
        }
    }
}

// ================= edge phase (warp per destination node, CSR) =============
__global__ __launch_bounds__(256)
void qagg_csr_kernel() {
    int node = (blockIdx.x * blockDim.x + threadIdx.x) >> 5;
    if (node >= N_NODES) return;
    int lane = threadIdx.x & 31;
    int beg = g_off[node], end = g_off[node + 1];

    float4 acc = make_float4(0.f, 0.f, 0.f, 0.f);
    for (int e0 = beg; e0 < end; e0 += 32) {
        int myc = (e0 + lane < end) ? g_ecol[e0 + lane] : 0;
        int n = min(32, end - e0);
        int j = 0;
        for (; j + 4 <= n; j += 4) {
#pragma unroll
            for (int u = 0; u < 4; u++) {
                int c = __shfl_sync(0xffffffffu, myc, j + u);
                const __half2* vp =
                    (const __half2*)(g_hq + (size_t)c * D + lane * 4);
                float2 f0 = __half22float2(vp[0]);
                float2 f1 = __half22float2(vp[1]);
                acc.x += f0.x; acc.y += f0.y;
                acc.z += f1.x; acc.w += f1.y;
            }
        }
        for (; j < n; j++) {
            int c = __shfl_sync(0xffffffffu, myc, j);
            const __half2* vp =
                (const __half2*)(g_hq + (size_t)c * D + lane * 4);
            float2 f0 = __half22float2(vp[0]);
            float2 f1 = __half22float2(vp[1]);
            acc.x += f0.x; acc.y += f0.y;
            acc.z += f1.x; acc.w += f1.y;
        }
    }
    __half2* qp = (__half2*)(g_qagg + (size_t)node * D + lane * 4);
    qp[0] = __floats2half2_rn(acc.x, acc.y);
    qp[1] = __floats2half2_rn(acc.z, acc.w);
}

__global__ __launch_bounds__(256)
void score_weighted_kernel(float* __restrict__ out) {
    int node = (blockIdx.x * blockDim.x + threadIdx.x) >> 5;
    if (node >= N_NODES) return;
    int lane = threadIdx.x & 31;
    int beg = g_off[node], end = g_off[node + 1];

    float4 k = *(const float4*)(g_kact + (size_t)node * D + lane * 4);
    float sum = 0.f;

    // pass 1: exp(score) per edge + replicated row sum (q_agg gathered fp16)
    for (int e0 = beg; e0 < end; e0 += 32) {
        int myc = (e0 + lane < end) ? g_ecol[e0 + lane] : 0;
        int n = min(32, end - e0);
        float myex = 0.f;
        int j = 0;
        for (; j + 4 <= n; j += 4) {
            float dd[4];
#pragma unroll
            for (int u = 0; u < 4; u++) {
                int c = __shfl_sync(0xffffffffu, myc, j + u);
                const __half2* qp =
                    (const __half2*)(g_qagg + (size_t)c * D + lane * 4);
                float2 q0 = __half22float2(qp[0]);
                float2 q1 = __half22float2(qp[1]);
                dd[u] = k.x * q0.x + k.y * q0.y + k.z * q1.x + k.w * q1.y;
            }
#pragma unroll
            for (int o = 16; o > 0; o >>= 1) {
#pragma unroll
                for (int u = 0; u < 4; u++)
                    dd[u] += __shfl_xor_sync(0xffffffffu, dd[u], o);
            }
#pragma unroll
            for (int u = 0; u < 4; u++) {
                float ex = __expf(dd[u] * INV_SQRT_D);
                sum += ex;
                if (lane == j + u) myex = ex;
            }
        }
        for (; j < n; j++) {
            int c = __shfl_sync(0xffffffffu, myc, j);
            const __half2* qp =
                (const __half2*)(g_qagg + (size_t)c * D + lane * 4);
            float2 q0 = __half22float2(qp[0]);
            float2 q1 = __half22float2(qp[1]);
            float d = k.x * q0.x + k.y * q0.y + k.z * q1.x + k.w * q1.y;
#pragma unroll
            for (int o = 16; o > 0; o >>= 1)
                d += __shfl_xor_sync(0xffffffffu, d, o);
            float ex = __expf(d * INV_SQRT_D);
            sum += ex;
            if (lane == j) myex = ex;
        }
        if (e0 + lane < end) g_escore[e0 + lane] = myex;
    }

    float rinv = 1.0f / (sum + 1e-8f);

    // pass 2: weighted aggregation of fp16 h_proj (8B per lane per edge)
    float4 acc = make_float4(0.f, 0.f, 0.f, 0.f);
    for (int e0 = beg; e0 < end; e0 += 32) {
        int in_range = (e0 + lane < end);
        int myc = in_range ? g_ecol[e0 + lane] : 0;
        float mya = in_range ? g_escore[e0 + lane] * rinv : 0.f;
        int n = min(32, end - e0);
        int j = 0;
        for (; j + 4 <= n; j += 4) {
#pragma unroll
            for (int u = 0; u < 4; u++) {
                int c = __shfl_sync(0xffffffffu, myc, j + u);
                float a = __shfl_sync(0xffffffffu, mya, j + u);
                const __half2* vp =
                    (const __half2*)(g_hproj + (size_t)c * D + lane * 4);
                float2 f0 = __half22float2(vp[0]);
                float2 f1 = __half22float2(vp[1]);
                acc.x += a * f0.x;
                acc.y += a * f0.y;
                acc.z += a * f1.x;
                acc.w += a * f1.y;
            }
        }
        for (; j < n; j++) {
            int c = __shfl_sync(0xffffffffu, myc, j);
            float a = __shfl_sync(0xffffffffu, mya, j);
            const __half2* vp =
                (const __half2*)(g_hproj + (size_t)c * D + lane * 4);
            float2 f0 = __half22float2(vp[0]);
            float2 f1 = __half22float2(vp[1]);
            acc.x += a * f0.x;
            acc.y += a * f0.y;
            acc.z += a * f1.x;
            acc.w += a * f1.y;
        }
    }
    acc.x = leaky(acc.x);
    acc.y = leaky(acc.y);
    acc.z = leaky(acc.z);
    acc.w = leaky(acc.w);
    *(float4*)(out + (size_t)node * D + lane * 4) = acc;

    // zero g_cnt for the NEXT launch (g_cnt is dead at this point this launch)
    if (lane == 0) g_cnt[node] = 0;
}

// ================= launch (serial; hist fused into GEMM grid) ==============
extern "C" void kernel_launch(void* const* d_in, const int* in_sizes, int n_in,
                              void* d_out, int out_size) {
    const float* x  = (const float*)d_in[0];
    const int*  ei  = (const int*)d_in[1];
    const float* Wq = (const float*)d_in[2];
    const float* Wk = (const float*)d_in[3];
    // d_in[4] = W_v : dead in reference
    const float* Wl = (const float*)d_in[5];
    const float* bl = (const float*)d_in[6];
    float* out = (float*)d_out;

    const int* row = ei;
    const int* col = ei + N_EDGES;

    const int eg = (N_EDGES + 255) / 256;
    const int ng = (N_NODES + 255) / 256;
    const int wg = (N_NODES * 32 + 255) / 256;

    wsplit_kernel<<<(3 * D * (D / 2) + 255) / 256, 256>>>(Wq, Wk, Wl);      // 0
    gemm3_hist_kernel<<<GEMM_BLOCKS + HIST_BLOCKS, 256>>>(x, bl, row);      // 1
    scan1_kernel<<<NBLK_SCAN, SCAN_CHUNK>>>();                              // 2
    scan2_kernel<<<1, 256>>>();                                             // 3
    scan3_kernel<<<ng, 256>>>();                                            // 4
    scatter_kernel<<<eg, 256>>>(row, col);                                  // 5
    qagg_csr_kernel<<<wg, 256>>>();                                         // 6
    score_weighted_kernel<<<wg, 256>>>(out);                                // 7
}

// round 17
// speedup vs baseline: 1.0474x; 1.0474x over previous
#include <cuda_runtime.h>
#include <cuda_fp16.h>
#include <math.h>
#include <stdint.h>

#define N_NODES 100000
#define N_EDGES 1600000
#define D 128
#define NEG_SLOPE 0.2f
#define INV_SQRT_D 0.08838834764831843f

#define SCAN_CHUNK 512
#define NBLK_SCAN ((N_NODES + SCAN_CHUNK - 1) / SCAN_CHUNK)   // 196

// ---------------- scratch (no allocs allowed) ----------------
__device__ __half g_hq[N_NODES * D];      // fp16: feeds qagg sum only
__device__ float  g_kact[N_NODES * D];    // fp32: score accuracy anchor
__device__ __half g_hproj[N_NODES * D];   // fp16: feeds alpha-weighted sum
__device__ __half g_qagg[N_NODES * D];    // fp16: gathered per edge in score pass
__device__ float  g_escore[N_EDGES];
__device__ int    g_cnt[N_NODES];         // zero at load; re-zeroed by score_weighted
__device__ int    g_off[N_NODES + 1];
__device__ int    g_cursor[N_NODES];
__device__ int    g_ecol[N_EDGES];
__device__ int    g_blocksum[NBLK_SCAN];
__device__ int    g_blockbase[NBLK_SCAN];
// W pre-split to bf16 hi/lo, [n][k-pair] layout packed bf16x2 (low16 = even k)
__device__ uint32_t g_Wbh[3 * D * (D / 2)];
__device__ uint32_t g_Wbl[3 * D * (D / 2)];

__device__ __forceinline__ float leaky(float v) {
    return v > 0.0f ? v : NEG_SLOPE * v;
}

__device__ __forceinline__ uint32_t pack_bf16(float lo_elem, float hi_elem) {
    uint32_t r;
    asm("cvt.rn.bf16x2.f32 %0, %1, %2;" : "=r"(r) : "f"(hi_elem), "f"(lo_elem));
    return r;
}
__device__ __forceinline__ float bf16hi_to_f(float v) {
    uint32_t r;
    asm("cvt.rn.bf16x2.f32 %0, %1, %2;" : "=r"(r) : "f"(0.f), "f"(v));
    return __uint_as_float(r << 16);
}
__device__ __forceinline__ void bf16split(float v, float& hi, float& lo) {
    hi = bf16hi_to_f(v);
    lo = v - hi;
}

// ================= W precompute (bf16 split, [n][kpair] layout) ============
__global__ void wsplit_kernel(const float* __restrict__ Wq,
                              const float* __restrict__ Wk,
                              const float* __restrict__ Wl) {
    int i = blockIdx.x * blockDim.x + threadIdx.x;
    if (i >= 3 * D * (D / 2)) return;
    int wi = i / (D * (D / 2));
    int rem = i % (D * (D / 2));
    int n = rem >> 6;
    int kp = rem & 63;
    const float* W = (wi == 0) ? Wq : ((wi == 1) ? Wk : Wl);
    float v0 = __ldg(W + (2 * kp) * D + n);
    float v1 = __ldg(W + (2 * kp + 1) * D + n);
    float h0, l0, h1, l1;
    bf16split(v0, h0, l0);
    bf16split(v1, h1, l1);
    g_Wbh[i] = pack_bf16(h0, h1);
    g_Wbl[i] = pack_bf16(l0, l1);
}

// ================= CSR build =================
__global__ void hist_kernel(const int* __restrict__ row) {
    int e = blockIdx.x * blockDim.x + threadIdx.x;
    if (e < N_EDGES) atomicAdd(&g_cnt[__ldg(row + e)], 1);
}

__global__ void scan1_kernel() {
    __shared__ int s[SCAN_CHUNK];
    int b = blockIdx.x, t = threadIdx.x;
    int i = b * SCAN_CHUNK + t;
    int v = (i < N_NODES) ? g_cnt[i] : 0;
    s[t] = v;
    __syncthreads();
    for (int off = 1; off < SCAN_CHUNK; off <<= 1) {
        int add = (t >= off) ? s[t - off] : 0;
        __syncthreads();
        s[t] += add;
        __syncthreads();
    }
    if (i < N_NODES) g_off[i] = s[t] - v;
    if (t == SCAN_CHUNK - 1) g_blocksum[b] = s[t];
}

__global__ void scan2_kernel() {
    __shared__ int s[256];
    int t = threadIdx.x;
    int v = (t < NBLK_SCAN) ? g_blocksum[t] : 0;
    s[t] = v;
    __syncthreads();
    for (int off = 1; off < 256; off <<= 1) {
        int add = (t >= off) ? s[t - off] : 0;
        __syncthreads();
        s[t] += add;
        __syncthreads();
    }
    if (t < NBLK_SCAN) g_blockbase[t] = s[t] - v;
}

__global__ void scan3_kernel() {
    int i = blockIdx.x * blockDim.x + threadIdx.x;
    if (i < N_NODES) {
        int o = g_off[i] + g_blockbase[i / SCAN_CHUNK];
        g_off[i] = o;
        g_cursor[i] = o;
    }
    if (i == 0) g_off[N_NODES] = N_EDGES;
}

__global__ void scatter_kernel(const int* __restrict__ row,
                               const int* __restrict__ col) {
    int e = blockIdx.x * blockDim.x + threadIdx.x;
    if (e >= N_EDGES) return;
    int r = __ldg(row + e);
    int pos = atomicAdd(&g_cursor[r], 1);
    g_ecol[pos] = __ldg(col + e);
}

// ================= bf16 split-3 tensor-core GEMM (round-6/9 proven) =======
#define GBM 128
#define GBK 32
#define LDP 20   // u32 row stride for [*][16] pair arrays; conflict-free

__device__ __forceinline__ void mma_bf16(float c[4], const uint32_t a[4],
                                         const uint32_t b0, const uint32_t b1) {
    asm volatile(
        "mma.sync.aligned.m16n8k16.row.col.f32.bf16.bf16.f32 "
        "{%0,%1,%2,%3}, {%4,%5,%6,%7}, {%8,%9}, {%0,%1,%2,%3};"
        : "+f"(c[0]), "+f"(c[1]), "+f"(c[2]), "+f"(c[3])
        : "r"(a[0]), "r"(a[1]), "r"(a[2]), "r"(a[3]), "r"(b0), "r"(b1));
}

__global__ __launch_bounds__(256, 2)
void gemm3_tc_kernel(const float* __restrict__ x,
                     const float* __restrict__ bl) {
    __shared__ uint32_t Ahi[GBM * LDP];   // [row][kpair]
    __shared__ uint32_t Alo[GBM * LDP];
    __shared__ uint32_t Whi[D * LDP];     // [n][kpair] for this k0 tile
    __shared__ uint32_t Wlo[D * LDP];

    const int wi = blockIdx.y;
    const uint32_t* __restrict__ gwh = g_Wbh + wi * D * (D / 2);
    const uint32_t* __restrict__ gwl = g_Wbl + wi * D * (D / 2);

    const int rowBase = blockIdx.x * GBM;
    const int tid = threadIdx.x;
    const int lane = tid & 31;
    const int warp = tid >> 5;
    const int m_base = (warp & 3) * 32;
    const int n_base = (warp >> 2) * 64;
    const int lq = lane >> 2;
    const int lr = lane & 3;

    float c[2][8][4];
#pragma unroll
    for (int mt = 0; mt < 2; mt++)
#pragma unroll
        for (int nt = 0; nt < 8; nt++)
#pragma unroll
            for (int i = 0; i < 4; i++) c[mt][nt][i] = 0.f;

    for (int k0 = 0; k0 < D; k0 += GBK) {
        const int kp0 = k0 / 2;
#pragma unroll
        for (int i = tid; i < (GBM * GBK) / 4; i += 256) {
            int r = i >> 3;
            int c4 = (i & 7) << 2;
            int gr = rowBase + r;
            float4 v = make_float4(0.f, 0.f, 0.f, 0.f);
            if (gr < N_NODES)
                v = *(const float4*)(x + (size_t)gr * D + k0 + c4);
            float h0, l0, h1, l1, h2, l2, h3, l3;
            bf16split(v.x, h0, l0);
            bf16split(v.y, h1, l1);
            bf16split(v.z, h2, l2);
            bf16split(v.w, h3, l3);
            int idx = r * LDP + (c4 >> 1);
            Ahi[idx + 0] = pack_bf16(h0, h1);
            Ahi[idx + 1] = pack_bf16(h2, h3);
            Alo[idx + 0] = pack_bf16(l0, l1);
            Alo[idx + 1] = pack_bf16(l2, l3);
        }
#pragma unroll
        for (int i = tid; i < (D * GBK / 2) / 4; i += 256) {
            int n = i >> 2;
            int pg = (i & 3) << 2;
            uint4 vh = *(const uint4*)(gwh + (size_t)n * (D / 2) + kp0 + pg);
            uint4 vl = *(const uint4*)(gwl + (size_t)n * (D / 2) + kp0 + pg);
            *(uint4*)&Whi[n * LDP + pg] = vh;
            *(uint4*)&Wlo[n * LDP + pg] = vl;
        }
        __syncthreads();

#pragma unroll
        for (int ks = 0; ks < GBK / 16; ks++) {
            const int kb = ks * 8;
            uint32_t a_hi[2][4], a_lo[2][4];
#pragma unroll
            for (int mt = 0; mt < 2; mt++) {
                int r0 = m_base + mt * 16 + lq;
                a_hi[mt][0] = Ahi[r0 * LDP + kb + lr];
                a_hi[mt][1] = Ahi[(r0 + 8) * LDP + kb + lr];
                a_hi[mt][2] = Ahi[r0 * LDP + kb + lr + 4];
                a_hi[mt][3] = Ahi[(r0 + 8) * LDP + kb + lr + 4];
                a_lo[mt][0] = Alo[r0 * LDP + kb + lr];
                a_lo[mt][1] = Alo[(r0 + 8) * LDP + kb + lr];
                a_lo[mt][2] = Alo[r0 * LDP + kb + lr + 4];
                a_lo[mt][3] = Alo[(r0 + 8) * LDP + kb + lr + 4];
            }
#pragma unroll
            for (int nt = 0; nt < 8; nt++) {
                int n0 = n_base + nt * 8 + lq;
                uint32_t b0h = Whi[n0 * LDP + kb + lr];
                uint32_t b1h = Whi[n0 * LDP + kb + lr + 4];
                uint32_t b0l = Wlo[n0 * LDP + kb + lr];
                uint32_t b1l = Wlo[n0 * LDP + kb + lr + 4];
#pragma unroll
                for (int mt = 0; mt < 2; mt++) {
                    mma_bf16(c[mt][nt], a_hi[mt], b0h, b1h);
                    mma_bf16(c[mt][nt], a_hi[mt], b0l, b1l);
                    mma_bf16(c[mt][nt], a_lo[mt], b0h, b1h);
                }
            }
        }
        __syncthreads();
    }

#pragma unroll
    for (int mt = 0; mt < 2; mt++) {
#pragma unroll
        for (int half = 0; half < 2; half++) {
            int gr = rowBase + m_base + mt * 16 + lq + half * 8;
            if (gr >= N_NODES) continue;
#pragma unroll
            for (int nt = 0; nt < 8; nt++) {
                int gc = n_base + nt * 8 + lr * 2;
                float v0 = c[mt][nt][half * 2 + 0];
                float v1 = c[mt][nt][half * 2 + 1];
                if (wi == 0) {
                    *(__half2*)(g_hq + (size_t)gr * D + gc) =
                        __floats2half2_rn(v0, v1);
                } else if (wi == 1) {
                    v0 = leaky(v0);
                    v1 = leaky(v1);
                    *(float2*)(g_kact + (size_t)gr * D + gc) = make_float2(v0, v1);
                } else {
                    v0 += __ldg(bl + gc + 0);
                    v1 += __ldg(bl + gc + 1);
                    *(__half2*)(g_hproj + (size_t)gr * D + gc) =
                        __floats2half2_rn(v0, v1);
                }
            }
        }
    }
}

// ================= edge phase (warp per destination node, CSR) =============
__global__ __launch_bounds__(256)
void qagg_csr_kernel() {
    int node = (blockIdx.x * blockDim.x + threadIdx.x) >> 5;
    if (node >= N_NODES) return;
    int lane = threadIdx.x & 31;
    int beg = g_off[node], end = g_off[node + 1];

    float4 acc = make_float4(0.f, 0.f, 0.f, 0.f);
    for (int e0 = beg; e0 < end; e0 += 32) {
        int myc = (e0 + lane < end) ? g_ecol[e0 + lane] : 0;
        int n = min(32, end - e0);
        int j = 0;
        for (; j + 4 <= n; j += 4) {
#pragma unroll
            for (int u = 0; u < 4; u++) {
                int c = __shfl_sync(0xffffffffu, myc, j + u);
                const __half2* vp =
                    (const __half2*)(g_hq + (size_t)c * D + lane * 4);
                float2 f0 = __half22float2(vp[0]);
                float2 f1 = __half22float2(vp[1]);
                acc.x += f0.x; acc.y += f0.y;
                acc.z += f1.x; acc.w += f1.y;
            }
        }
        for (; j < n; j++) {
            int c = __shfl_sync(0xffffffffu, myc, j);
            const __half2* vp =
                (const __half2*)(g_hq + (size_t)c * D + lane * 4);
            float2 f0 = __half22float2(vp[0]);
            float2 f1 = __half22float2(vp[1]);
            acc.x += f0.x; acc.y += f0.y;
            acc.z += f1.x; acc.w += f1.y;
        }
    }
    __half2* qp = (__half2*)(g_qagg + (size_t)node * D + lane * 4);
    qp[0] = __floats2half2_rn(acc.x, acc.y);
    qp[1] = __floats2half2_rn(acc.z, acc.w);
}

__global__ __launch_bounds__(256)
void score_weighted_kernel(float* __restrict__ out) {
    int node = (blockIdx.x * blockDim.x + threadIdx.x) >> 5;
    if (node >= N_NODES) return;
    int lane = threadIdx.x & 31;
    int beg = g_off[node], end = g_off[node + 1];

    float4 k = *(const float4*)(g_kact + (size_t)node * D + lane * 4);
    float sum = 0.f;

    // pass 1: exp(score) per edge + replicated row sum (q_agg gathered fp16)
    for (int e0 = beg; e0 < end; e0 += 32) {
        int myc = (e0 + lane < end) ? g_ecol[e0 + lane] : 0;
        int n = min(32, end - e0);
        float myex = 0.f;
        int j = 0;
        for (; j + 4 <= n; j += 4) {
            float dd[4];
#pragma unroll
            for (int u = 0; u < 4; u++) {
                int c = __shfl_sync(0xffffffffu, myc, j + u);
                const __half2* qp =
                    (const __half2*)(g_qagg + (size_t)c * D + lane * 4);
                float2 q0 = __half22float2(qp[0]);
                float2 q1 = __half22float2(qp[1]);
                dd[u] = k.x * q0.x + k.y * q0.y + k.z * q1.x + k.w * q1.y;
            }
#pragma unroll
            for (int o = 16; o > 0; o >>= 1) {
#pragma unroll
                for (int u = 0; u < 4; u++)
                    dd[u] += __shfl_xor_sync(0xffffffffu, dd[u], o);
            }
#pragma unroll
            for (int u = 0; u < 4; u++) {
                float ex = __expf(dd[u] * INV_SQRT_D);
                sum += ex;
                if (lane == j + u) myex = ex;
            }
        }
        for (; j < n; j++) {
            int c = __shfl_sync(0xffffffffu, myc, j);
            const __half2* qp =
                (const __half2*)(g_qagg + (size_t)c * D + lane * 4);
            float2 q0 = __half22float2(qp[0]);
            float2 q1 = __half22float2(qp[1]);
            float d = k.x * q0.x + k.y * q0.y + k.z * q1.x + k.w * q1.y;
#pragma unroll
            for (int o = 16; o > 0; o >>= 1)
                d += __shfl_xor_sync(0xffffffffu, d, o);
            float ex = __expf(d * INV_SQRT_D);
            sum += ex;
            if (lane == j) myex = ex;
        }
        if (e0 + lane < end) g_escore[e0 + lane] = myex;
    }

    float rinv = 1.0f / (sum + 1e-8f);

    // pass 2: weighted aggregation of fp16 h_proj (8B per lane per edge)
    float4 acc = make_float4(0.f, 0.f, 0.f, 0.f);
    for (int e0 = beg; e0 < end; e0 += 32) {
        int in_range = (e0 + lane < end);
        int myc = in_range ? g_ecol[e0 + lane] : 0;
        float mya = in_range ? g_escore[e0 + lane] * rinv : 0.f;
        int n = min(32, end - e0);
        int j = 0;
        for (; j + 4 <= n; j += 4) {
#pragma unroll
            for (int u = 0; u < 4; u++) {
                int c = __shfl_sync(0xffffffffu, myc, j + u);
                float a = __shfl_sync(0xffffffffu, mya, j + u);
                const __half2* vp =
                    (const __half2*)(g_hproj + (size_t)c * D + lane * 4);
                float2 f0 = __half22float2(vp[0]);
                float2 f1 = __half22float2(vp[1]);
                acc.x += a * f0.x;
                acc.y += a * f0.y;
                acc.z += a * f1.x;
                acc.w += a * f1.y;
            }
        }
        for (; j < n; j++) {
            int c = __shfl_sync(0xffffffffu, myc, j);
            float a = __shfl_sync(0xffffffffu, mya, j);
            const __half2* vp =
                (const __half2*)(g_hproj + (size_t)c * D + lane * 4);
            float2 f0 = __half22float2(vp[0]);
            float2 f1 = __half22float2(vp[1]);
            acc.x += a * f0.x;
            acc.y += a * f0.y;
            acc.z += a * f1.x;
            acc.w += a * f1.y;
        }
    }
    acc.x = leaky(acc.x);
    acc.y = leaky(acc.y);
    acc.z = leaky(acc.z);
    acc.w = leaky(acc.w);
    *(float4*)(out + (size_t)node * D + lane * 4) = acc;

    // zero g_cnt for the NEXT launch (this node's counter is dead now;
    // validated across graph replays in round 16)
    if (lane == 0) g_cnt[node] = 0;
}

// ================= launch (serial, round-14 proven ordering; no zero pass) =
extern "C" void kernel_launch(void* const* d_in, const int* in_sizes, int n_in,
                              void* d_out, int out_size) {
    const float* x  = (const float*)d_in[0];
    const int*  ei  = (const int*)d_in[1];
    const float* Wq = (const float*)d_in[2];
    const float* Wk = (const float*)d_in[3];
    // d_in[4] = W_v : dead in reference
    const float* Wl = (const float*)d_in[5];
    const float* bl = (const float*)d_in[6];
    float* out = (float*)d_out;

    const int* row = ei;
    const int* col = ei + N_EDGES;

    const int eg = (N_EDGES + 255) / 256;
    const int ng = (N_NODES + 255) / 256;
    const int wg = (N_NODES * 32 + 255) / 256;

    wsplit_kernel<<<(3 * D * (D / 2) + 255) / 256, 256>>>(Wq, Wk, Wl);  // 0
    hist_kernel<<<eg, 256>>>(row);                                      // 1
    {
        dim3 grid((N_NODES + GBM - 1) / GBM, 3);
        gemm3_tc_kernel<<<grid, 256>>>(x, bl);                          // 2
    }
    scan1_kernel<<<NBLK_SCAN, SCAN_CHUNK>>>();                          // 3
    scan2_kernel<<<1, 256>>>();                                         // 4
    scan3_kernel<<<ng, 256>>>();                                        // 5
    scatter_kernel<<<eg, 256>>>(row, col);                              // 6
    qagg_csr_kernel<<<wg, 256>>>();                                     // 7
    score_weighted_kernel<<<wg, 256>>>(out);                            // 8
}